// round 3
// baseline (speedup 1.0000x reference)
#include <cuda_runtime.h>
#include <cuda_bf16.h>
#include <math.h>
#include <stdint.h>

// ---------------- problem dims ----------------
#define BB   128
#define TT   64
#define SS   40
#define DD   256
#define HH   256
#define NG   1024          // 4*H
#define BT   (BB*TT)       // 8192

// ---------------- output layout (float32, concatenated tuple) ----------------
#define OG_OFF   0
#define FAKE_OFF 256
#define DEC_OFF  512
#define GEN_OFF  (DEC_OFF + BT*DD)
#define STS_OFF  (GEN_OFF + BT*DD)
#define LBL_OFF  (STS_OFF + BB*TT)

// ---------------- scratch (device globals; no allocations) ----------------
__device__ float g_v[BT*DD];         // embedded inputs  [bt][d]
__device__ float g_xg[TT*BB*NG];     // input gates      [t][b][g]
__device__ float g_h1[BT*HH];        // lstm1 h          [bt][u]
__device__ float g_h2[BT*HH];        // lstm2 h          [bt][u]
__device__ float g_wh[BT*HH];        // h1 @ Whk^T + bhk [bt][k]
__device__ float g_bar[BT*DD];       // bar_v            [bt][d]
__device__ float g_wz[BT*64];        // wh @ W1b^T       [bt][j]
__device__ float g_ez[BB*64];        // e  @ W1a^T + b1  [b][j]
__device__ float g_t1[128*1024];
__device__ float g_t2[128*512];
__device__ float g_hwork[2*4*HH*32]; // h exchange [phase][bg][u][bl]
__device__ unsigned int g_barrier;

// ---------------- packed f32x2 FMA ----------------
__device__ __forceinline__ void fma2(float2& d, float2 a, float2 b)
{
    unsigned long long dd, aa, bb;
    dd = *reinterpret_cast<unsigned long long*>(&d);
    aa = *reinterpret_cast<unsigned long long*>(&a);
    bb = *reinterpret_cast<unsigned long long*>(&b);
    asm("fma.rn.f32x2 %0, %1, %2, %0;" : "+l"(dd) : "l"(aa), "l"(bb));
    d = *reinterpret_cast<float2*>(&dd);
}

__device__ __forceinline__ float fsig(float x)
{
    return __fdividef(1.f, 1.f + __expf(-x));
}
__device__ __forceinline__ float ftanh(float x)
{
    // tanh(x) = 2*sigmoid(2x) - 1  (abs err ~1e-6)
    return fmaf(2.f, __fdividef(1.f, 1.f + __expf(-2.f * x)), -1.f);
}

// =======================================================================
// embedding gather + relu + sum over S
// =======================================================================
__global__ void embed_kernel(const int* __restrict__ seqs, const float* __restrict__ emb)
{
    __shared__ int idx[SS];
    const int bv = blockIdx.x;
    const int d  = threadIdx.x;
    if (d < SS) idx[d] = seqs[bv*SS + d];
    __syncthreads();
    float acc = 0.f;
#pragma unroll 8
    for (int s = 0; s < SS; s++) {
        float e = emb[(size_t)idx[s]*DD + d];
        acc += fmaxf(e, 0.f);
    }
    g_v[(size_t)bv*DD + d] = acc;
}

// =======================================================================
// tiled fp32 GEMM (f32x2 packed): C = act(A @ W^T + bias [+ bias2])
//   mode 0: C[m*N + n]
//   mode 1: C[t*BB*N + b*N + n] with b=m>>6, t=m&63   (xg layout [t][b][g])
// =======================================================================
#define GBM 64
#define GBN 64
#define GBK 16
__global__ void __launch_bounds__(256)
gemm_kernel(const float* __restrict__ A, int lda,
            const float* __restrict__ W, int ldw,
            const float* __restrict__ bias, const float* __restrict__ bias2,
            float* __restrict__ C, int K, int N, int mode, int act)
{
    __shared__ float2 As2[GBK][GBM];       // duplicated A values (8 KB)
    __shared__ float  Bs[GBK][GBN + 4];
    const int m0 = blockIdx.y * GBM;
    const int n0 = blockIdx.x * GBN;
    const int tid = threadIdx.x;
    const int tx = tid & 15;           // n dir (4 cols)
    const int ty = tid >> 4;           // m dir (4 rows)
    const int lr  = tid >> 2;          // loader row 0..63
    const int lk4 = tid & 3;           // loader k-quad

    const float* Aload = A + (size_t)(m0 + lr) * lda + lk4 * 4;
    const float* Wload = W + (size_t)(n0 + lr) * ldw + lk4 * 4;

    float2 acc[4][2];
#pragma unroll
    for (int i = 0; i < 4; i++) { acc[i][0] = make_float2(0.f,0.f); acc[i][1] = make_float2(0.f,0.f); }

    for (int k0 = 0; k0 < K; k0 += GBK) {
        float4 av = *(const float4*)(Aload + k0);
        float4 wv = *(const float4*)(Wload + k0);
        if (k0) __syncthreads();
        As2[lk4*4+0][lr] = make_float2(av.x, av.x);
        As2[lk4*4+1][lr] = make_float2(av.y, av.y);
        As2[lk4*4+2][lr] = make_float2(av.z, av.z);
        As2[lk4*4+3][lr] = make_float2(av.w, av.w);
        Bs[lk4*4+0][lr] = wv.x; Bs[lk4*4+1][lr] = wv.y;
        Bs[lk4*4+2][lr] = wv.z; Bs[lk4*4+3][lr] = wv.w;
        __syncthreads();
#pragma unroll
        for (int k = 0; k < GBK; k++) {
            float2 a0 = As2[k][ty*4+0];
            float2 a1 = As2[k][ty*4+1];
            float2 a2 = As2[k][ty*4+2];
            float2 a3 = As2[k][ty*4+3];
            float4 bq = *(const float4*)&Bs[k][tx*4];
            float2 b01 = make_float2(bq.x, bq.y);
            float2 b23 = make_float2(bq.z, bq.w);
            fma2(acc[0][0], a0, b01); fma2(acc[0][1], a0, b23);
            fma2(acc[1][0], a1, b01); fma2(acc[1][1], a1, b23);
            fma2(acc[2][0], a2, b01); fma2(acc[2][1], a2, b23);
            fma2(acc[3][0], a3, b01); fma2(acc[3][1], a3, b23);
        }
    }

#pragma unroll
    for (int i = 0; i < 4; i++) {
        int m = m0 + ty*4 + i;
        int nb = n0 + tx*4;
        float4 res = make_float4(acc[i][0].x, acc[i][0].y, acc[i][1].x, acc[i][1].y);
        if (bias)  { res.x += bias[nb];  res.y += bias[nb+1];  res.z += bias[nb+2];  res.w += bias[nb+3]; }
        if (bias2) { res.x += bias2[nb]; res.y += bias2[nb+1]; res.z += bias2[nb+2]; res.w += bias2[nb+3]; }
        if (act) {
            res.x = fmaxf(res.x, 0.f); res.y = fmaxf(res.y, 0.f);
            res.z = fmaxf(res.z, 0.f); res.w = fmaxf(res.w, 0.f);
        }
        float* dst;
        if (mode == 0) dst = C + (size_t)m * N + nb;
        else {
            int b = m >> 6, t = m & 63;
            dst = C + (size_t)t * (BB*N) + (size_t)b * N + nb;
        }
        *(float4*)dst = res;
    }
}

// =======================================================================
// persistent LSTM: 128 blocks = 32 hidden-groups x 4 batch-groups
// block owns 8 hidden units x 32 batch. 256 threads:
//   up = tid&3 (unit pair), half = (tid>>2)&1 (K half), bl = tid>>3 (batch)
// smem: h duplicated [256][32] float2 (64KB) + W_hh packed (32KB)
// =======================================================================
#define LSTM_SMEM (96*1024)

__global__ void reset_kernel() { if (threadIdx.x == 0) g_barrier = 0u; }

__global__ void __launch_bounds__(256, 1)
lstm_kernel(const float* __restrict__ xg,
            const float* __restrict__ Whh,
            float* __restrict__ h_all)
{
    extern __shared__ float sm[];
    float2* h_dup = (float2*)sm;                  // [j 256][bl 32] duplicated
    float4* w4 = (float4*)(sm + 2*256*32);        // [j 256][up 4][e 2] gates(i,f,g,o)

    const int tid  = threadIdx.x;
    const int up   = tid & 3;
    const int half = (tid >> 2) & 1;
    const int bl   = tid >> 3;                    // 0..31
    const int hg   = blockIdx.x >> 2;             // 0..31
    const int bg   = blockIdx.x & 3;              // 0..3
    const int u0   = hg * 8;
    const int ua   = u0 + up*2;                   // even
    const int b    = bg*32 + bl;

    // pack W_hh: w4[j*8 + r] = gates for unit u0+r at input j
    for (int i = tid; i < 256*8; i += 256) {
        int j = i >> 3, r = i & 7;
        int u = u0 + r;
        w4[i] = make_float4(Whh[(size_t)(0*HH+u)*HH + j],
                            Whh[(size_t)(1*HH+u)*HH + j],
                            Whh[(size_t)(2*HH+u)*HH + j],
                            Whh[(size_t)(3*HH+u)*HH + j]);
    }
    for (int i = tid; i < 256*32; i += 256) h_dup[i] = make_float2(0.f, 0.f);
    float ca = 0.f, cb = 0.f;
    unsigned target = 128;
    __syncthreads();

    const int j0 = half * 128;
    for (int t = 0; t < TT; t++) {
        // prefetch input gates for this (b, units ua, ua+1)
        const float* xb = xg + (size_t)t * (BB*NG) + (size_t)b * NG;
        float2 x_i = *(const float2*)(xb + 0*HH + ua);
        float2 x_f = *(const float2*)(xb + 1*HH + ua);
        float2 x_g = *(const float2*)(xb + 2*HH + ua);
        float2 x_o = *(const float2*)(xb + 3*HH + ua);

        float2 aif = make_float2(0.f,0.f), ago = make_float2(0.f,0.f);
        float2 bif = make_float2(0.f,0.f), bgo = make_float2(0.f,0.f);
#pragma unroll 8
        for (int j = j0; j < j0 + 128; j++) {
            float2 hd = h_dup[j*32 + bl];
            float4 wa = w4[j*8 + up*2 + 0];
            float4 wb = w4[j*8 + up*2 + 1];
            fma2(aif, hd, make_float2(wa.x, wa.y));
            fma2(ago, hd, make_float2(wa.z, wa.w));
            fma2(bif, hd, make_float2(wb.x, wb.y));
            fma2(bgo, hd, make_float2(wb.z, wb.w));
        }
        // combine K-halves: partner lane = lane ^ 4
        aif.x += __shfl_xor_sync(0xffffffffu, aif.x, 4);
        aif.y += __shfl_xor_sync(0xffffffffu, aif.y, 4);
        ago.x += __shfl_xor_sync(0xffffffffu, ago.x, 4);
        ago.y += __shfl_xor_sync(0xffffffffu, ago.y, 4);
        bif.x += __shfl_xor_sync(0xffffffffu, bif.x, 4);
        bif.y += __shfl_xor_sync(0xffffffffu, bif.y, 4);
        bgo.x += __shfl_xor_sync(0xffffffffu, bgo.x, 4);
        bgo.y += __shfl_xor_sync(0xffffffffu, bgo.y, 4);

        float gia = aif.x + x_i.x, gfa = aif.y + x_f.x;
        float gga = ago.x + x_g.x, goa = ago.y + x_o.x;
        float gib = bif.x + x_i.y, gfb = bif.y + x_f.y;
        float ggb = bgo.x + x_g.y, gob = bgo.y + x_o.y;

        ca = fsig(gfa) * ca + fsig(gia) * ftanh(gga);
        cb = fsig(gfb) * cb + fsig(gib) * ftanh(ggb);
        float ha = fsig(goa) * ftanh(ca);
        float hb = fsig(gob) * ftanh(cb);

        float* hw = g_hwork + ((size_t)((t & 1)*4 + bg)) * (HH*32);
        if (half == 0) {
            *(float2*)&h_all[((size_t)b*TT + t)*HH + ua] = make_float2(ha, hb);
            __stcg(&hw[(ua  )*32 + bl], ha);
            __stcg(&hw[(ua+1)*32 + bl], hb);
        }

        if (t == TT-1) break;

        // grid barrier
        __syncthreads();
        if (tid == 0) {
            __threadfence();
            atomicAdd(&g_barrier, 1u);
            volatile unsigned* barp = (volatile unsigned*)&g_barrier;
            while (*barp < target) { }
        }
        __syncthreads();
        target += 128;

        // stage next h (our batch slice only), duplicated into smem
        const float4* src = (const float4*)hw;
        for (int i = tid; i < (HH*32)/4; i += 256) {
            float4 v = __ldcg(src + i);
            float2* dst = h_dup + (i >> 3)*32 + (i & 7)*4;
            dst[0] = make_float2(v.x, v.x);
            dst[1] = make_float2(v.y, v.y);
            dst[2] = make_float2(v.z, v.z);
            dst[3] = make_float2(v.w, v.w);
        }
        __syncthreads();
    }
}

// =======================================================================
// attention finalize: per (b, t=0..62), softmax over 2 and blend
// =======================================================================
__global__ void attn_kernel(const float* __restrict__ W2,
                            const float* __restrict__ b2,
                            float* __restrict__ out)
{
    const int idx = blockIdx.x;
    const int b = idx / 63;
    const int t = idx % 63;
    const int tid = threadIdx.x;
    __shared__ float z1[64];
    __shared__ float a01[2];

    if (tid < 64) {
        float z = g_ez[b*64 + tid] + g_wz[((size_t)b*TT + t)*64 + tid];
        z1[tid] = tanhf(z);
    }
    __syncthreads();
    if (tid < 32) {
        float x0 = z1[tid], x1 = z1[tid + 32];
        float s0 = x0 * W2[tid]      + x1 * W2[tid + 32];
        float s1 = x0 * W2[64 + tid] + x1 * W2[96 + tid];
#pragma unroll
        for (int off = 16; off; off >>= 1) {
            s0 += __shfl_xor_sync(0xffffffffu, s0, off);
            s1 += __shfl_xor_sync(0xffffffffu, s1, off);
        }
        if (tid == 0) {
            s0 += b2[0]; s1 += b2[1];
            float m = fmaxf(s0, s1);
            float e0 = expf(s0 - m), e1 = expf(s1 - m);
            float inv = 1.f / (e0 + e1);
            a01[0] = e0 * inv; a01[1] = e1 * inv;
        }
    }
    __syncthreads();
    float e = g_v[(size_t)b*TT*DD + tid];
    float w = g_wh[((size_t)b*TT + t)*HH + tid];
    float bv = e * a01[0] + w * a01[1];
    size_t o = ((size_t)b*TT + t + 1)*DD + tid;
    g_bar[o] = bv;
    out[DEC_OFF + o] = bv;
    out[GEN_OFF + o] = bv;
}

// =======================================================================
// passthroughs: bar_v row t=0, seq_time_step, label
// =======================================================================
__global__ void tail_kernel(const float* __restrict__ sts,
                            const int* __restrict__ label,
                            float* __restrict__ out)
{
    const int b = blockIdx.x, tid = threadIdx.x;
    float val = g_v[(size_t)b*TT*DD + tid];
    size_t o = (size_t)b*TT*DD + tid;
    g_bar[o] = val;
    out[DEC_OFF + o] = val;
    out[GEN_OFF + o] = val;
    if (tid < TT) out[STS_OFF + b*TT + tid] = sts[b*TT + tid];
    if (tid == 0) out[LBL_OFF + b] = (float)label[b];
}

// =======================================================================
// warp-per-output FC (tiny N=2 head): C = A @ W^T + bias
// =======================================================================
__global__ void fc_kernel(const float* __restrict__ A, int lda,
                          const float* __restrict__ W, int ldw,
                          const float* __restrict__ bias,
                          float* __restrict__ C, int ldc,
                          int M, int N, int K)
{
    int gw = (blockIdx.x * blockDim.x + threadIdx.x) >> 5;
    int lane = threadIdx.x & 31;
    if (gw >= M * N) return;
    int m = gw / N, n = gw % N;
    const float* a = A + (size_t)m * lda;
    const float* w = W + (size_t)n * ldw;
    float acc = 0.f;
    for (int k = lane * 4; k < K; k += 128) {
        float4 av = *(const float4*)(a + k);
        float4 wv = *(const float4*)(w + k);
        acc += av.x*wv.x + av.y*wv.y + av.z*wv.z + av.w*wv.w;
    }
#pragma unroll
    for (int off = 16; off; off >>= 1) acc += __shfl_xor_sync(0xffffffffu, acc, off);
    if (lane == 0) C[(size_t)m * ldc + n] = acc + bias[n];
}

// =======================================================================
// host launcher
// =======================================================================
extern "C" void kernel_launch(void* const* d_in, const int* in_sizes, int n_in,
                              void* d_out, int out_size)
{
    (void)in_sizes; (void)n_in; (void)out_size;
    const int*   seqs  = (const int*)  d_in[0];
    const float* sts   = (const float*)d_in[3];
    const int*   label = (const int*)  d_in[5];
    const float* emb   = (const float*)d_in[6];
    const float* W_ih  = (const float*)d_in[7];
    const float* W_hh  = (const float*)d_in[8];
    const float* b_ih  = (const float*)d_in[9];
    const float* b_hh  = (const float*)d_in[10];
    const float* Whk   = (const float*)d_in[11];
    const float* bhk   = (const float*)d_in[12];
    const float* W1    = (const float*)d_in[13];
    const float* b1    = (const float*)d_in[14];
    const float* W2    = (const float*)d_in[15];
    const float* b2    = (const float*)d_in[16];
    const float* C1W   = (const float*)d_in[17];
    const float* C1b   = (const float*)d_in[18];
    const float* C2W   = (const float*)d_in[19];
    const float* C2b   = (const float*)d_in[20];
    const float* CoW   = (const float*)d_in[21];
    const float* Cob   = (const float*)d_in[22];
    float* out = (float*)d_out;

    cudaFuncSetAttribute(lstm_kernel, cudaFuncAttributeMaxDynamicSharedMemorySize, LSTM_SMEM);

    float *p_v, *p_xg, *p_h1, *p_h2, *p_wh, *p_bar, *p_wz, *p_ez, *p_t1, *p_t2;
    cudaGetSymbolAddress((void**)&p_v,   g_v);
    cudaGetSymbolAddress((void**)&p_xg,  g_xg);
    cudaGetSymbolAddress((void**)&p_h1,  g_h1);
    cudaGetSymbolAddress((void**)&p_h2,  g_h2);
    cudaGetSymbolAddress((void**)&p_wh,  g_wh);
    cudaGetSymbolAddress((void**)&p_bar, g_bar);
    cudaGetSymbolAddress((void**)&p_wz,  g_wz);
    cudaGetSymbolAddress((void**)&p_ez,  g_ez);
    cudaGetSymbolAddress((void**)&p_t1,  g_t1);
    cudaGetSymbolAddress((void**)&p_t2,  g_t2);

    // 1. embed
    embed_kernel<<<BT, 256>>>(seqs, emb);

    // 2. xg1 = v @ W_ih^T + b_ih + b_hh   -> [t][b][g]
    gemm_kernel<<<dim3(NG/64, BT/64), 256>>>(p_v, DD, W_ih, DD, b_ih, b_hh,
                                             p_xg, DD, NG, 1, 0);
    // 3. LSTM1
    reset_kernel<<<1, 32>>>();
    lstm_kernel<<<128, 256, LSTM_SMEM>>>(p_xg, W_hh, p_h1);

    // 4. wh = h1 @ Whk^T + bhk
    gemm_kernel<<<dim3(HH/64, BT/64), 256>>>(p_h1, HH, Whk, HH, bhk, nullptr,
                                             p_wh, HH, HH, 0, 0);
    // 5. wz = wh @ W1[:,256:]^T
    gemm_kernel<<<dim3(1, BT/64), 256>>>(p_wh, HH, W1 + 256, 512, nullptr, nullptr,
                                         p_wz, HH, 64, 0, 0);
    // 6. ez = v[:,0,:] @ W1[:,:256]^T + b1
    gemm_kernel<<<dim3(1, 2), 256>>>(p_v, TT*DD, W1, 512, b1, nullptr,
                                     p_ez, DD, 64, 0, 0);
    // 7. bar_v rows t=1..63 + Dec/Gen outputs; row t=0 + passthroughs
    attn_kernel<<<BB*63, 256>>>(W2, b2, out);
    tail_kernel<<<BB, 256>>>(sts, label, out);

    // 8. xg2 = bar_v @ W_ih^T + b_ih + b_hh
    gemm_kernel<<<dim3(NG/64, BT/64), 256>>>(p_bar, DD, W_ih, DD, b_ih, b_hh,
                                             p_xg, DD, NG, 1, 0);
    // 9. LSTM2
    reset_kernel<<<1, 32>>>();
    lstm_kernel<<<128, 256, LSTM_SMEM>>>(p_xg, W_hh, p_h2);

    // 10. classify og (h1 at t=63)
    gemm_kernel<<<dim3(1024/64, 2), 256>>>(p_h1 + 63*HH, TT*HH, C1W, HH, C1b, nullptr,
                                           p_t1, HH, 1024, 0, 1);
    gemm_kernel<<<dim3(512/64, 2), 256>>>(p_t1, 1024, C2W, 1024, C2b, nullptr,
                                          p_t2, 1024, 512, 0, 1);
    fc_kernel<<<(128*2*32 + 255)/256, 256>>>(p_t2, 512, CoW, 512, Cob,
                                             out + OG_OFF, 2, 128, 2, 512);

    // 11. classify fake (h2 at t=63)
    gemm_kernel<<<dim3(1024/64, 2), 256>>>(p_h2 + 63*HH, TT*HH, C1W, HH, C1b, nullptr,
                                           p_t1, HH, 1024, 0, 1);
    gemm_kernel<<<dim3(512/64, 2), 256>>>(p_t1, 1024, C2W, 1024, C2b, nullptr,
                                          p_t2, 1024, 512, 0, 1);
    fc_kernel<<<(128*2*32 + 255)/256, 256>>>(p_t2, 512, CoW, 512, Cob,
                                             out + FAKE_OFF, 2, 128, 2, 512);
}

// round 5
// speedup vs baseline: 1.0007x; 1.0007x over previous
#include <cuda_runtime.h>
#include <cuda_bf16.h>
#include <math.h>
#include <stdint.h>

// ---------------- problem dims ----------------
#define BB   128
#define TT   64
#define SS   40
#define DD   256
#define HH   256
#define NG   1024          // 4*H
#define BT   (BB*TT)       // 8192

// ---------------- output layout (float32, concatenated tuple) ----------------
#define OG_OFF   0
#define FAKE_OFF 256
#define DEC_OFF  512
#define GEN_OFF  (DEC_OFF + BT*DD)
#define STS_OFF  (GEN_OFF + BT*DD)
#define LBL_OFF  (STS_OFF + BB*TT)

// ---------------- scratch (device globals; no allocations) ----------------
__device__ float g_v[BT*DD];         // embedded inputs  [bt][d]
__device__ float g_xg[TT*BB*NG];     // input gates      [t][b][g]
__device__ float g_h1[BT*HH];        // lstm1 h          [bt][u]
__device__ float g_h2[BT*HH];        // lstm2 h          [bt][u]
__device__ float g_wh[BT*HH];        // h1 @ Whk^T + bhk [bt][k]
__device__ float g_bar[BT*DD];       // bar_v            [bt][d]
__device__ float g_wz[BT*64];        // wh @ W1b^T       [bt][j]
__device__ float g_ez[BB*64];        // e  @ W1a^T + b1  [b][j]
__device__ float g_t1[128*1024];
__device__ float g_t2[128*512];
__device__ float g_hwork[2*4*HH*32]; // h exchange [phase][bg][u][bl]
__device__ unsigned int g_barrier;

// ---------------- packed f32x2 FMA ----------------
__device__ __forceinline__ void fma2(float2& d, float2 a, float2 b)
{
    unsigned long long dd, aa, bb;
    dd = *reinterpret_cast<unsigned long long*>(&d);
    aa = *reinterpret_cast<unsigned long long*>(&a);
    bb = *reinterpret_cast<unsigned long long*>(&b);
    asm("fma.rn.f32x2 %0, %1, %2, %0;" : "+l"(dd) : "l"(aa), "l"(bb));
    d = *reinterpret_cast<float2*>(&dd);
}

__device__ __forceinline__ float fsig(float x)
{
    return __fdividef(1.f, 1.f + __expf(-x));
}
__device__ __forceinline__ float ftanh(float x)
{
    // tanh(x) = 2*sigmoid(2x) - 1  (abs err ~1e-6)
    return fmaf(2.f, __fdividef(1.f, 1.f + __expf(-2.f * x)), -1.f);
}

// =======================================================================
// embedding gather + relu + sum over S
// =======================================================================
__global__ void embed_kernel(const int* __restrict__ seqs, const float* __restrict__ emb)
{
    __shared__ int idx[SS];
    const int bv = blockIdx.x;
    const int d  = threadIdx.x;
    if (d < SS) idx[d] = seqs[bv*SS + d];
    __syncthreads();
    float acc = 0.f;
#pragma unroll 8
    for (int s = 0; s < SS; s++) {
        float e = emb[(size_t)idx[s]*DD + d];
        acc += fmaxf(e, 0.f);
    }
    g_v[(size_t)bv*DD + d] = acc;
}

// =======================================================================
// tiled fp32 GEMM (f32x2 packed): C = act(A @ W^T + bias [+ bias2])
//   mode 0: C[m*N + n]
//   mode 1: C[t*BB*N + b*N + n] with b=m>>6, t=m&63   (xg layout [t][b][g])
// =======================================================================
#define GBM 64
#define GBN 64
#define GBK 16
__global__ void __launch_bounds__(256)
gemm_kernel(const float* __restrict__ A, int lda,
            const float* __restrict__ W, int ldw,
            const float* __restrict__ bias, const float* __restrict__ bias2,
            float* __restrict__ C, int K, int N, int mode, int act)
{
    __shared__ float2 As2[GBK][GBM];       // duplicated A values (8 KB)
    __shared__ float  Bs[GBK][GBN + 4];
    const int m0 = blockIdx.y * GBM;
    const int n0 = blockIdx.x * GBN;
    const int tid = threadIdx.x;
    const int tx = tid & 15;           // n dir (4 cols)
    const int ty = tid >> 4;           // m dir (4 rows)
    const int lr  = tid >> 2;          // loader row 0..63
    const int lk4 = tid & 3;           // loader k-quad

    const float* Aload = A + (size_t)(m0 + lr) * lda + lk4 * 4;
    const float* Wload = W + (size_t)(n0 + lr) * ldw + lk4 * 4;

    float2 acc[4][2];
#pragma unroll
    for (int i = 0; i < 4; i++) { acc[i][0] = make_float2(0.f,0.f); acc[i][1] = make_float2(0.f,0.f); }

    for (int k0 = 0; k0 < K; k0 += GBK) {
        float4 av = *(const float4*)(Aload + k0);
        float4 wv = *(const float4*)(Wload + k0);
        if (k0) __syncthreads();
        As2[lk4*4+0][lr] = make_float2(av.x, av.x);
        As2[lk4*4+1][lr] = make_float2(av.y, av.y);
        As2[lk4*4+2][lr] = make_float2(av.z, av.z);
        As2[lk4*4+3][lr] = make_float2(av.w, av.w);
        Bs[lk4*4+0][lr] = wv.x; Bs[lk4*4+1][lr] = wv.y;
        Bs[lk4*4+2][lr] = wv.z; Bs[lk4*4+3][lr] = wv.w;
        __syncthreads();
#pragma unroll
        for (int k = 0; k < GBK; k++) {
            float2 a0 = As2[k][ty*4+0];
            float2 a1 = As2[k][ty*4+1];
            float2 a2 = As2[k][ty*4+2];
            float2 a3 = As2[k][ty*4+3];
            float4 bq = *(const float4*)&Bs[k][tx*4];
            float2 b01 = make_float2(bq.x, bq.y);
            float2 b23 = make_float2(bq.z, bq.w);
            fma2(acc[0][0], a0, b01); fma2(acc[0][1], a0, b23);
            fma2(acc[1][0], a1, b01); fma2(acc[1][1], a1, b23);
            fma2(acc[2][0], a2, b01); fma2(acc[2][1], a2, b23);
            fma2(acc[3][0], a3, b01); fma2(acc[3][1], a3, b23);
        }
    }

#pragma unroll
    for (int i = 0; i < 4; i++) {
        int m = m0 + ty*4 + i;
        int nb = n0 + tx*4;
        float4 res = make_float4(acc[i][0].x, acc[i][0].y, acc[i][1].x, acc[i][1].y);
        if (bias)  { res.x += bias[nb];  res.y += bias[nb+1];  res.z += bias[nb+2];  res.w += bias[nb+3]; }
        if (bias2) { res.x += bias2[nb]; res.y += bias2[nb+1]; res.z += bias2[nb+2]; res.w += bias2[nb+3]; }
        if (act) {
            res.x = fmaxf(res.x, 0.f); res.y = fmaxf(res.y, 0.f);
            res.z = fmaxf(res.z, 0.f); res.w = fmaxf(res.w, 0.f);
        }
        float* dst;
        if (mode == 0) dst = C + (size_t)m * N + nb;
        else {
            int b = m >> 6, t = m & 63;
            dst = C + (size_t)t * (BB*N) + (size_t)b * N + nb;
        }
        *(float4*)dst = res;
    }
}

// =======================================================================
// persistent LSTM: 128 blocks = 32 hidden-groups x 4 batch-groups
// block owns 8 hidden units x 32 batch. 256 threads:
//   up = tid&3 (unit pair), half = (tid>>2)&1 (K half), bl = tid>>3 (batch)
// smem: h duplicated [256][32] float2 (64KB) + W_hh packed (32KB)
// =======================================================================
#define LSTM_SMEM (96*1024)

__global__ void reset_kernel() { if (threadIdx.x == 0) g_barrier = 0u; }

__global__ void __launch_bounds__(256, 1)
lstm_kernel(const float* __restrict__ xg,
            const float* __restrict__ Whh,
            float* __restrict__ h_all)
{
    extern __shared__ float sm[];
    float2* h_dup = (float2*)sm;                  // [j 256][bl 32] duplicated
    float4* w4 = (float4*)(sm + 2*256*32);        // [j 256][up 4][e 2] gates(i,f,g,o)

    const int tid  = threadIdx.x;
    const int up   = tid & 3;
    const int half = (tid >> 2) & 1;
    const int bl   = tid >> 3;                    // 0..31
    const int hg   = blockIdx.x >> 2;             // 0..31
    const int bg   = blockIdx.x & 3;              // 0..3
    const int u0   = hg * 8;
    const int ua   = u0 + up*2;                   // even
    const int b    = bg*32 + bl;

    // pack W_hh: w4[j*8 + r] = gates for unit u0+r at input j
    for (int i = tid; i < 256*8; i += 256) {
        int j = i >> 3, r = i & 7;
        int u = u0 + r;
        w4[i] = make_float4(Whh[(size_t)(0*HH+u)*HH + j],
                            Whh[(size_t)(1*HH+u)*HH + j],
                            Whh[(size_t)(2*HH+u)*HH + j],
                            Whh[(size_t)(3*HH+u)*HH + j]);
    }
    for (int i = tid; i < 256*32; i += 256) h_dup[i] = make_float2(0.f, 0.f);
    float ca = 0.f, cb = 0.f;
    unsigned target = 128;
    __syncthreads();

    const int j0 = half * 128;
    for (int t = 0; t < TT; t++) {
        // prefetch input gates for this (b, units ua, ua+1)
        const float* xb = xg + (size_t)t * (BB*NG) + (size_t)b * NG;
        float2 x_i = *(const float2*)(xb + 0*HH + ua);
        float2 x_f = *(const float2*)(xb + 1*HH + ua);
        float2 x_g = *(const float2*)(xb + 2*HH + ua);
        float2 x_o = *(const float2*)(xb + 3*HH + ua);

        float2 aif = make_float2(0.f,0.f), ago = make_float2(0.f,0.f);
        float2 bif = make_float2(0.f,0.f), bgo = make_float2(0.f,0.f);
#pragma unroll 8
        for (int j = j0; j < j0 + 128; j++) {
            float2 hd = h_dup[j*32 + bl];
            float4 wa = w4[j*8 + up*2 + 0];
            float4 wb = w4[j*8 + up*2 + 1];
            fma2(aif, hd, make_float2(wa.x, wa.y));
            fma2(ago, hd, make_float2(wa.z, wa.w));
            fma2(bif, hd, make_float2(wb.x, wb.y));
            fma2(bgo, hd, make_float2(wb.z, wb.w));
        }
        // combine K-halves: partner lane = lane ^ 4
        aif.x += __shfl_xor_sync(0xffffffffu, aif.x, 4);
        aif.y += __shfl_xor_sync(0xffffffffu, aif.y, 4);
        ago.x += __shfl_xor_sync(0xffffffffu, ago.x, 4);
        ago.y += __shfl_xor_sync(0xffffffffu, ago.y, 4);
        bif.x += __shfl_xor_sync(0xffffffffu, bif.x, 4);
        bif.y += __shfl_xor_sync(0xffffffffu, bif.y, 4);
        bgo.x += __shfl_xor_sync(0xffffffffu, bgo.x, 4);
        bgo.y += __shfl_xor_sync(0xffffffffu, bgo.y, 4);

        float gia = aif.x + x_i.x, gfa = aif.y + x_f.x;
        float gga = ago.x + x_g.x, goa = ago.y + x_o.x;
        float gib = bif.x + x_i.y, gfb = bif.y + x_f.y;
        float ggb = bgo.x + x_g.y, gob = bgo.y + x_o.y;

        ca = fsig(gfa) * ca + fsig(gia) * ftanh(gga);
        cb = fsig(gfb) * cb + fsig(gib) * ftanh(ggb);
        float ha = fsig(goa) * ftanh(ca);
        float hb = fsig(gob) * ftanh(cb);

        float* hw = g_hwork + ((size_t)((t & 1)*4 + bg)) * (HH*32);
        if (half == 0) {
            *(float2*)&h_all[((size_t)b*TT + t)*HH + ua] = make_float2(ha, hb);
            __stcg(&hw[(ua  )*32 + bl], ha);
            __stcg(&hw[(ua+1)*32 + bl], hb);
        }

        if (t == TT-1) break;

        // grid barrier
        __syncthreads();
        if (tid == 0) {
            __threadfence();
            atomicAdd(&g_barrier, 1u);
            volatile unsigned* barp = (volatile unsigned*)&g_barrier;
            while (*barp < target) { }
        }
        __syncthreads();
        target += 128;

        // stage next h (our batch slice only), duplicated into smem
        const float4* src = (const float4*)hw;
        for (int i = tid; i < (HH*32)/4; i += 256) {
            float4 v = __ldcg(src + i);
            float2* dst = h_dup + (i >> 3)*32 + (i & 7)*4;
            dst[0] = make_float2(v.x, v.x);
            dst[1] = make_float2(v.y, v.y);
            dst[2] = make_float2(v.z, v.z);
            dst[3] = make_float2(v.w, v.w);
        }
        __syncthreads();
    }
}

// =======================================================================
// attention finalize: per (b, t=0..62), softmax over 2 and blend
// =======================================================================
__global__ void attn_kernel(const float* __restrict__ W2,
                            const float* __restrict__ b2,
                            float* __restrict__ out)
{
    const int idx = blockIdx.x;
    const int b = idx / 63;
    const int t = idx % 63;
    const int tid = threadIdx.x;
    __shared__ float z1[64];
    __shared__ float a01[2];

    if (tid < 64) {
        float z = g_ez[b*64 + tid] + g_wz[((size_t)b*TT + t)*64 + tid];
        z1[tid] = tanhf(z);
    }
    __syncthreads();
    if (tid < 32) {
        float x0 = z1[tid], x1 = z1[tid + 32];
        float s0 = x0 * W2[tid]      + x1 * W2[tid + 32];
        float s1 = x0 * W2[64 + tid] + x1 * W2[96 + tid];
#pragma unroll
        for (int off = 16; off; off >>= 1) {
            s0 += __shfl_xor_sync(0xffffffffu, s0, off);
            s1 += __shfl_xor_sync(0xffffffffu, s1, off);
        }
        if (tid == 0) {
            s0 += b2[0]; s1 += b2[1];
            float m = fmaxf(s0, s1);
            float e0 = expf(s0 - m), e1 = expf(s1 - m);
            float inv = 1.f / (e0 + e1);
            a01[0] = e0 * inv; a01[1] = e1 * inv;
        }
    }
    __syncthreads();
    float e = g_v[(size_t)b*TT*DD + tid];
    float w = g_wh[((size_t)b*TT + t)*HH + tid];
    float bv = e * a01[0] + w * a01[1];
    size_t o = ((size_t)b*TT + t + 1)*DD + tid;
    g_bar[o] = bv;
    out[DEC_OFF + o] = bv;
    out[GEN_OFF + o] = bv;
}

// =======================================================================
// passthroughs: bar_v row t=0, seq_time_step, label
// =======================================================================
__global__ void tail_kernel(const float* __restrict__ sts,
                            const int* __restrict__ label,
                            float* __restrict__ out)
{
    const int b = blockIdx.x, tid = threadIdx.x;
    float val = g_v[(size_t)b*TT*DD + tid];
    size_t o = (size_t)b*TT*DD + tid;
    g_bar[o] = val;
    out[DEC_OFF + o] = val;
    out[GEN_OFF + o] = val;
    if (tid < TT) out[STS_OFF + b*TT + tid] = sts[b*TT + tid];
    if (tid == 0) out[LBL_OFF + b] = (float)label[b];
}

// =======================================================================
// warp-per-output FC (tiny N=2 head): C = A @ W^T + bias
// =======================================================================
__global__ void fc_kernel(const float* __restrict__ A, int lda,
                          const float* __restrict__ W, int ldw,
                          const float* __restrict__ bias,
                          float* __restrict__ C, int ldc,
                          int M, int N, int K)
{
    int gw = (blockIdx.x * blockDim.x + threadIdx.x) >> 5;
    int lane = threadIdx.x & 31;
    if (gw >= M * N) return;
    int m = gw / N, n = gw % N;
    const float* a = A + (size_t)m * lda;
    const float* w = W + (size_t)n * ldw;
    float acc = 0.f;
    for (int k = lane * 4; k < K; k += 128) {
        float4 av = *(const float4*)(a + k);
        float4 wv = *(const float4*)(w + k);
        acc += av.x*wv.x + av.y*wv.y + av.z*wv.z + av.w*wv.w;
    }
#pragma unroll
    for (int off = 16; off; off >>= 1) acc += __shfl_xor_sync(0xffffffffu, acc, off);
    if (lane == 0) C[(size_t)m * ldc + n] = acc + bias[n];
}

// =======================================================================
// host launcher
// =======================================================================
extern "C" void kernel_launch(void* const* d_in, const int* in_sizes, int n_in,
                              void* d_out, int out_size)
{
    (void)in_sizes; (void)n_in; (void)out_size;
    const int*   seqs  = (const int*)  d_in[0];
    const float* sts   = (const float*)d_in[3];
    const int*   label = (const int*)  d_in[5];
    const float* emb   = (const float*)d_in[6];
    const float* W_ih  = (const float*)d_in[7];
    const float* W_hh  = (const float*)d_in[8];
    const float* b_ih  = (const float*)d_in[9];
    const float* b_hh  = (const float*)d_in[10];
    const float* Whk   = (const float*)d_in[11];
    const float* bhk   = (const float*)d_in[12];
    const float* W1    = (const float*)d_in[13];
    const float* b1    = (const float*)d_in[14];
    const float* W2    = (const float*)d_in[15];
    const float* b2    = (const float*)d_in[16];
    const float* C1W   = (const float*)d_in[17];
    const float* C1b   = (const float*)d_in[18];
    const float* C2W   = (const float*)d_in[19];
    const float* C2b   = (const float*)d_in[20];
    const float* CoW   = (const float*)d_in[21];
    const float* Cob   = (const float*)d_in[22];
    float* out = (float*)d_out;

    cudaFuncSetAttribute(lstm_kernel, cudaFuncAttributeMaxDynamicSharedMemorySize, LSTM_SMEM);

    float *p_v, *p_xg, *p_h1, *p_h2, *p_wh, *p_bar, *p_wz, *p_ez, *p_t1, *p_t2;
    cudaGetSymbolAddress((void**)&p_v,   g_v);
    cudaGetSymbolAddress((void**)&p_xg,  g_xg);
    cudaGetSymbolAddress((void**)&p_h1,  g_h1);
    cudaGetSymbolAddress((void**)&p_h2,  g_h2);
    cudaGetSymbolAddress((void**)&p_wh,  g_wh);
    cudaGetSymbolAddress((void**)&p_bar, g_bar);
    cudaGetSymbolAddress((void**)&p_wz,  g_wz);
    cudaGetSymbolAddress((void**)&p_ez,  g_ez);
    cudaGetSymbolAddress((void**)&p_t1,  g_t1);
    cudaGetSymbolAddress((void**)&p_t2,  g_t2);

    // 1. embed
    embed_kernel<<<BT, 256>>>(seqs, emb);

    // 2. xg1 = v @ W_ih^T + b_ih + b_hh   -> [t][b][g]
    gemm_kernel<<<dim3(NG/64, BT/64), 256>>>(p_v, DD, W_ih, DD, b_ih, b_hh,
                                             p_xg, DD, NG, 1, 0);
    // 3. LSTM1
    reset_kernel<<<1, 32>>>();
    lstm_kernel<<<128, 256, LSTM_SMEM>>>(p_xg, W_hh, p_h1);

    // 4. wh = h1 @ Whk^T + bhk
    gemm_kernel<<<dim3(HH/64, BT/64), 256>>>(p_h1, HH, Whk, HH, bhk, nullptr,
                                             p_wh, HH, HH, 0, 0);
    // 5. wz = wh @ W1[:,256:]^T
    gemm_kernel<<<dim3(1, BT/64), 256>>>(p_wh, HH, W1 + 256, 512, nullptr, nullptr,
                                         p_wz, HH, 64, 0, 0);
    // 6. ez = v[:,0,:] @ W1[:,:256]^T + b1
    gemm_kernel<<<dim3(1, 2), 256>>>(p_v, TT*DD, W1, 512, b1, nullptr,
                                     p_ez, DD, 64, 0, 0);
    // 7. bar_v rows t=1..63 + Dec/Gen outputs; row t=0 + passthroughs
    attn_kernel<<<BB*63, 256>>>(W2, b2, out);
    tail_kernel<<<BB, 256>>>(sts, label, out);

    // 8. xg2 = bar_v @ W_ih^T + b_ih + b_hh
    gemm_kernel<<<dim3(NG/64, BT/64), 256>>>(p_bar, DD, W_ih, DD, b_ih, b_hh,
                                             p_xg, DD, NG, 1, 0);
    // 9. LSTM2
    reset_kernel<<<1, 32>>>();
    lstm_kernel<<<128, 256, LSTM_SMEM>>>(p_xg, W_hh, p_h2);

    // 10. classify og (h1 at t=63)
    gemm_kernel<<<dim3(1024/64, 2), 256>>>(p_h1 + 63*HH, TT*HH, C1W, HH, C1b, nullptr,
                                           p_t1, HH, 1024, 0, 1);
    gemm_kernel<<<dim3(512/64, 2), 256>>>(p_t1, 1024, C2W, 1024, C2b, nullptr,
                                          p_t2, 1024, 512, 0, 1);
    fc_kernel<<<(128*2*32 + 255)/256, 256>>>(p_t2, 512, CoW, 512, Cob,
                                             out + OG_OFF, 2, 128, 2, 512);

    // 11. classify fake (h2 at t=63)
    gemm_kernel<<<dim3(1024/64, 2), 256>>>(p_h2 + 63*HH, TT*HH, C1W, HH, C1b, nullptr,
                                           p_t1, HH, 1024, 0, 1);
    gemm_kernel<<<dim3(512/64, 2), 256>>>(p_t1, 1024, C2W, 1024, C2b, nullptr,
                                          p_t2, 1024, 512, 0, 1);
    fc_kernel<<<(128*2*32 + 255)/256, 256>>>(p_t2, 512, CoW, 512, Cob,
                                             out + FAKE_OFF, 2, 128, 2, 512);
}

// round 7
// speedup vs baseline: 2.0360x; 2.0346x over previous
#include <cuda_runtime.h>
#include <math.h>
#include <stdint.h>

#define BB   128
#define TT   64
#define SS   40
#define DD   256
#define HH   256
#define NG   1024
#define BT   (BB*TT)

#define OG_OFF   0
#define FAKE_OFF 256
#define DEC_OFF  512
#define GEN_OFF  (DEC_OFF + BT*DD)
#define STS_OFF  (GEN_OFF + BT*DD)
#define LBL_OFF  (STS_OFF + BB*TT)

__device__ float g_v[BT*DD];
__device__ float g_xg[TT*BB*NG];     // [t][b][u*4+gate]
__device__ float g_h1[BT*HH];
__device__ float g_h2[BT*HH];
__device__ float g_wh[BT*HH];
__device__ float g_bar[BT*DD];
__device__ float g_wz[BT*64];
__device__ float g_ez[BB*64];
__device__ float g_t1[128*1024];
__device__ float g_t2[128*512];
__device__ float g_hwork[2*4*HH*32]; // [phase][bg][u][b32]
__device__ unsigned int g_barrier;

__device__ __forceinline__ void fma2(float2& d, float2 a, float2 b)
{
    unsigned long long dd = *(unsigned long long*)&d;
    unsigned long long aa = *(unsigned long long*)&a;
    unsigned long long bb = *(unsigned long long*)&b;
    asm("fma.rn.f32x2 %0, %1, %2, %0;" : "+l"(dd) : "l"(aa), "l"(bb));
    d = *(float2*)&dd;
}
__device__ __forceinline__ float fsig(float x) { return __fdividef(1.f, 1.f + __expf(-x)); }
__device__ __forceinline__ float ftanh(float x) { return fmaf(2.f, __fdividef(1.f, 1.f + __expf(-2.f*x)), -1.f); }
__device__ __forceinline__ void red2(float2& v, int off)
{
    v.x += __shfl_xor_sync(0xffffffffu, v.x, off);
    v.y += __shfl_xor_sync(0xffffffffu, v.y, off);
}

// ---------------- embed ----------------
__global__ void embed_kernel(const int* __restrict__ seqs, const float* __restrict__ emb)
{
    __shared__ int idx[SS];
    const int bv = blockIdx.x, d = threadIdx.x;
    if (d < SS) idx[d] = seqs[bv*SS + d];
    __syncthreads();
    float acc = 0.f;
#pragma unroll 8
    for (int s = 0; s < SS; s++) acc += fmaxf(emb[(size_t)idx[s]*DD + d], 0.f);
    g_v[(size_t)bv*DD + d] = acc;
}

// ---------------- 64x64 GEMM: C = act(A@W^T + bias [+bias2]) ----------------
// mode 0: C[m*N+n]; mode 1 (N=1024): xg layout C[t*BB*NG + b*NG + u*4 + gate]
#define GBK 16
__global__ void __launch_bounds__(256)
gemm_kernel(const float* __restrict__ A, int lda,
            const float* __restrict__ W, int ldw,
            const float* __restrict__ bias, const float* __restrict__ bias2,
            float* __restrict__ C, int K, int N, int mode, int act)
{
    __shared__ float As[GBK][65];
    __shared__ float Bs[GBK][68];
    const int m0 = blockIdx.y*64, n0 = blockIdx.x*64;
    const int tid = threadIdx.x;
    const int tx = tid & 15, ty = tid >> 4;
    const int lr = tid >> 2, lk4 = tid & 3;
    const float* Aload = A + (size_t)(m0+lr)*lda + lk4*4;
    const float* Wload = W + (size_t)(n0+lr)*ldw + lk4*4;
    float acc[4][4] = {};
    for (int k0 = 0; k0 < K; k0 += GBK) {
        float4 av = *(const float4*)(Aload + k0);
        float4 wv = *(const float4*)(Wload + k0);
        if (k0) __syncthreads();
        As[lk4*4+0][lr]=av.x; As[lk4*4+1][lr]=av.y; As[lk4*4+2][lr]=av.z; As[lk4*4+3][lr]=av.w;
        Bs[lk4*4+0][lr]=wv.x; Bs[lk4*4+1][lr]=wv.y; Bs[lk4*4+2][lr]=wv.z; Bs[lk4*4+3][lr]=wv.w;
        __syncthreads();
#pragma unroll
        for (int k = 0; k < GBK; k++) {
            float a0=As[k][ty*4], a1=As[k][ty*4+1], a2=As[k][ty*4+2], a3=As[k][ty*4+3];
            float4 bv = *(const float4*)&Bs[k][tx*4];
            acc[0][0]=fmaf(a0,bv.x,acc[0][0]); acc[0][1]=fmaf(a0,bv.y,acc[0][1]);
            acc[0][2]=fmaf(a0,bv.z,acc[0][2]); acc[0][3]=fmaf(a0,bv.w,acc[0][3]);
            acc[1][0]=fmaf(a1,bv.x,acc[1][0]); acc[1][1]=fmaf(a1,bv.y,acc[1][1]);
            acc[1][2]=fmaf(a1,bv.z,acc[1][2]); acc[1][3]=fmaf(a1,bv.w,acc[1][3]);
            acc[2][0]=fmaf(a2,bv.x,acc[2][0]); acc[2][1]=fmaf(a2,bv.y,acc[2][1]);
            acc[2][2]=fmaf(a2,bv.z,acc[2][2]); acc[2][3]=fmaf(a2,bv.w,acc[2][3]);
            acc[3][0]=fmaf(a3,bv.x,acc[3][0]); acc[3][1]=fmaf(a3,bv.y,acc[3][1]);
            acc[3][2]=fmaf(a3,bv.z,acc[3][2]); acc[3][3]=fmaf(a3,bv.w,acc[3][3]);
        }
    }
#pragma unroll
    for (int i = 0; i < 4; i++)
#pragma unroll
        for (int j = 0; j < 4; j++) {
            int m = m0 + ty*4 + i, n = n0 + tx*4 + j;
            float val = acc[i][j];
            if (bias)  val += bias[n];
            if (bias2) val += bias2[n];
            if (act)   val = fmaxf(val, 0.f);
            if (mode == 0) C[(size_t)m*N + n] = val;
            else {
                int b = m >> 6, t = m & 63;
                C[((size_t)t*BB + b)*NG + (n & (HH-1))*4 + (n >> 8)] = val;
            }
        }
}

// ---------------- persistent LSTM: weights in registers ----------------
__global__ void reset_kernel() { if (threadIdx.x == 0) g_barrier = 0u; }

__global__ void __launch_bounds__(256, 1)
lstm_kernel(const float* __restrict__ xg, const float* __restrict__ Whh,
            float* __restrict__ h_all)
{
    __shared__ float h_sm[256*36];               // h rows, stride 36 (conflict-free)
    const int tid = threadIdx.x;
    const int lane = tid & 31;
    const int ks  = lane & 7;                    // K-slice
    const int bpg = lane >> 3;                   // batch quad
    const int rg  = tid >> 5;                    // warp = unit
    const int hg  = blockIdx.x >> 2, bg = blockIdx.x & 3;
    const int u0  = hg*8, u = u0 + rg;
    const int bb  = lane;                        // own batch = bpg*8+ks = lane
    const int b   = bg*32 + bb;

    // W_hh slice -> 128 registers (staged through smem)
    float wr[4][32];
    {
        float* wtmp = h_sm;                      // [32 rows][256]
        for (int c = tid; c < 2048; c += 256) {
            int ro = c >> 6, jq = c & 63;        // ro = gate*8+ru
            *(float4*)&wtmp[ro*256 + jq*4] =
                *(const float4*)&Whh[(size_t)((ro>>3)*HH + u0 + (ro&7))*HH + jq*4];
        }
        __syncthreads();
#pragma unroll
        for (int g = 0; g < 4; g++)
#pragma unroll
            for (int jj = 0; jj < 32; jj++)
                wr[g][jj] = wtmp[(g*8 + rg)*256 + jj*8 + ks];
        __syncthreads();
    }
    for (int i = tid; i < 256*36; i += 256) h_sm[i] = 0.f;
    float cst = 0.f;
    unsigned target = 128;
    __syncthreads();

    for (int t = 0; t < TT; t++) {
        float4 xgv = *(const float4*)&xg[((size_t)t*BB + b)*NG + u*4];

        float2 acc[4][4];
#pragma unroll
        for (int g = 0; g < 4; g++)
#pragma unroll
            for (int p = 0; p < 4; p++) acc[g][p] = make_float2(0.f, 0.f);

#pragma unroll
        for (int jj = 0; jj < 32; jj++) {
            const float* hp = &h_sm[(jj*8 + ks)*36 + bpg*8];
            float4 h0 = *(const float4*)hp;
            float4 h1 = *(const float4*)(hp + 4);
            float2 hp0 = make_float2(h0.x, h0.y), hp1 = make_float2(h0.z, h0.w);
            float2 hp2 = make_float2(h1.x, h1.y), hp3 = make_float2(h1.z, h1.w);
#pragma unroll
            for (int g = 0; g < 4; g++) {
                float2 w2 = make_float2(wr[g][jj], wr[g][jj]);
                fma2(acc[g][0], w2, hp0); fma2(acc[g][1], w2, hp1);
                fma2(acc[g][2], w2, hp2); fma2(acc[g][3], w2, hp3);
            }
        }
        // reduce over ks (lane bits 0..2)
#pragma unroll
        for (int off = 1; off <= 4; off <<= 1)
#pragma unroll
            for (int g = 0; g < 4; g++) {
                red2(acc[g][0], off); red2(acc[g][1], off);
                red2(acc[g][2], off); red2(acc[g][3], off);
            }
        // select own batch (predicated, no dynamic reg indexing)
        float gv[4];
#pragma unroll
        for (int g = 0; g < 4; g++) {
            float2 lo = (ks & 2) ? acc[g][1] : acc[g][0];
            float2 hi = (ks & 2) ? acc[g][3] : acc[g][2];
            float2 s  = (ks & 4) ? hi : lo;
            gv[g] = (ks & 1) ? s.y : s.x;
        }
        float gi = gv[0] + xgv.x, gf = gv[1] + xgv.y;
        float gg = gv[2] + xgv.z, go = gv[3] + xgv.w;
        cst = fsig(gf)*cst + fsig(gi)*ftanh(gg);
        float h = fsig(go)*ftanh(cst);

        h_all[((size_t)b*TT + t)*HH + u] = h;
        float* hw = g_hwork + (size_t)((t & 1)*4 + bg)*(HH*32);
        __stcg(&hw[u*32 + bb], h);

        if (t == TT-1) break;

        __syncthreads();
        if (tid == 0) {
            __threadfence();
            atomicAdd(&g_barrier, 1u);
            volatile unsigned* barp = (volatile unsigned*)&g_barrier;
            while (*barp < target) { }
        }
        __syncthreads();
        target += 128;

        const float4* src = (const float4*)hw;
#pragma unroll
        for (int r = 0; r < 8; r++) {
            int c = tid + 256*r;                 // 0..2047
            float4 v = __ldcg(src + c);
            *(float4*)&h_sm[(c >> 3)*36 + (c & 7)*4] = v;
        }
        __syncthreads();
    }
}

// ---------------- attention finalize ----------------
__global__ void attn_kernel(const float* __restrict__ W2, const float* __restrict__ b2,
                            float* __restrict__ out)
{
    const int b = blockIdx.x / 63, t = blockIdx.x % 63;
    const int tid = threadIdx.x;
    __shared__ float z1[64];
    __shared__ float a01[2];
    if (tid < 64) z1[tid] = tanhf(g_ez[b*64 + tid] + g_wz[((size_t)b*TT + t)*64 + tid]);
    __syncthreads();
    if (tid < 32) {
        float x0 = z1[tid], x1 = z1[tid + 32];
        float s0 = x0*W2[tid]    + x1*W2[tid+32];
        float s1 = x0*W2[64+tid] + x1*W2[96+tid];
#pragma unroll
        for (int off = 16; off; off >>= 1) {
            s0 += __shfl_xor_sync(0xffffffffu, s0, off);
            s1 += __shfl_xor_sync(0xffffffffu, s1, off);
        }
        if (tid == 0) {
            s0 += b2[0]; s1 += b2[1];
            float m = fmaxf(s0, s1);
            float e0 = expf(s0-m), e1 = expf(s1-m);
            float inv = 1.f/(e0+e1);
            a01[0] = e0*inv; a01[1] = e1*inv;
        }
    }
    __syncthreads();
    float e = g_v[(size_t)b*TT*DD + tid];
    float w = g_wh[((size_t)b*TT + t)*HH + tid];
    float bv = e*a01[0] + w*a01[1];
    size_t o = ((size_t)b*TT + t + 1)*DD + tid;
    g_bar[o] = bv; out[DEC_OFF + o] = bv; out[GEN_OFF + o] = bv;
}

__global__ void tail_kernel(const float* __restrict__ sts, const int* __restrict__ label,
                            float* __restrict__ out)
{
    const int b = blockIdx.x, tid = threadIdx.x;
    float val = g_v[(size_t)b*TT*DD + tid];
    size_t o = (size_t)b*TT*DD + tid;
    g_bar[o] = val; out[DEC_OFF + o] = val; out[GEN_OFF + o] = val;
    if (tid < TT) out[STS_OFF + b*TT + tid] = sts[b*TT + tid];
    if (tid == 0) out[LBL_OFF + b] = (float)label[b];
}

__global__ void fc_kernel(const float* __restrict__ A, int lda,
                          const float* __restrict__ W, int ldw,
                          const float* __restrict__ bias,
                          float* __restrict__ C, int ldc, int M, int N, int K)
{
    int gw = (blockIdx.x*blockDim.x + threadIdx.x) >> 5;
    int lane = threadIdx.x & 31;
    if (gw >= M*N) return;
    int m = gw / N, n = gw % N;
    const float* a = A + (size_t)m*lda;
    const float* w = W + (size_t)n*ldw;
    float acc = 0.f;
    for (int k = lane*4; k < K; k += 128) {
        float4 av = *(const float4*)(a+k);
        float4 wv = *(const float4*)(w+k);
        acc += av.x*wv.x + av.y*wv.y + av.z*wv.z + av.w*wv.w;
    }
#pragma unroll
    for (int off = 16; off; off >>= 1) acc += __shfl_xor_sync(0xffffffffu, acc, off);
    if (lane == 0) C[(size_t)m*ldc + n] = acc + bias[n];
}

extern "C" void kernel_launch(void* const* d_in, const int* in_sizes, int n_in,
                              void* d_out, int out_size)
{
    (void)in_sizes; (void)n_in; (void)out_size;
    const int*   seqs  = (const int*)  d_in[0];
    const float* sts   = (const float*)d_in[3];
    const int*   label = (const int*)  d_in[5];
    const float* emb   = (const float*)d_in[6];
    const float* W_ih  = (const float*)d_in[7];
    const float* W_hh  = (const float*)d_in[8];
    const float* b_ih  = (const float*)d_in[9];
    const float* b_hh  = (const float*)d_in[10];
    const float* Whk   = (const float*)d_in[11];
    const float* bhk   = (const float*)d_in[12];
    const float* W1    = (const float*)d_in[13];
    const float* b1    = (const float*)d_in[14];
    const float* W2    = (const float*)d_in[15];
    const float* b2    = (const float*)d_in[16];
    const float* C1W   = (const float*)d_in[17];
    const float* C1b   = (const float*)d_in[18];
    const float* C2W   = (const float*)d_in[19];
    const float* C2b   = (const float*)d_in[20];
    const float* CoW   = (const float*)d_in[21];
    const float* Cob   = (const float*)d_in[22];
    float* out = (float*)d_out;

    float *p_v, *p_xg, *p_h1, *p_h2, *p_wh, *p_bar, *p_wz, *p_ez, *p_t1, *p_t2;
    cudaGetSymbolAddress((void**)&p_v, g_v);
    cudaGetSymbolAddress((void**)&p_xg, g_xg);
    cudaGetSymbolAddress((void**)&p_h1, g_h1);
    cudaGetSymbolAddress((void**)&p_h2, g_h2);
    cudaGetSymbolAddress((void**)&p_wh, g_wh);
    cudaGetSymbolAddress((void**)&p_bar, g_bar);
    cudaGetSymbolAddress((void**)&p_wz, g_wz);
    cudaGetSymbolAddress((void**)&p_ez, g_ez);
    cudaGetSymbolAddress((void**)&p_t1, g_t1);
    cudaGetSymbolAddress((void**)&p_t2, g_t2);

    embed_kernel<<<BT, 256>>>(seqs, emb);

    gemm_kernel<<<dim3(NG/64, BT/64), 256>>>(p_v, DD, W_ih, DD, b_ih, b_hh,
                                             p_xg, DD, NG, 1, 0);
    reset_kernel<<<1, 32>>>();
    lstm_kernel<<<128, 256>>>(p_xg, W_hh, p_h1);

    gemm_kernel<<<dim3(HH/64, BT/64), 256>>>(p_h1, HH, Whk, HH, bhk, nullptr,
                                             p_wh, HH, HH, 0, 0);
    gemm_kernel<<<dim3(1, BT/64), 256>>>(p_wh, HH, W1 + 256, 512, nullptr, nullptr,
                                         p_wz, HH, 64, 0, 0);
    gemm_kernel<<<dim3(1, 2), 256>>>(p_v, TT*DD, W1, 512, b1, nullptr,
                                     p_ez, DD, 64, 0, 0);
    attn_kernel<<<BB*63, 256>>>(W2, b2, out);
    tail_kernel<<<BB, 256>>>(sts, label, out);

    gemm_kernel<<<dim3(NG/64, BT/64), 256>>>(p_bar, DD, W_ih, DD, b_ih, b_hh,
                                             p_xg, DD, NG, 1, 0);
    reset_kernel<<<1, 32>>>();
    lstm_kernel<<<128, 256>>>(p_xg, W_hh, p_h2);

    gemm_kernel<<<dim3(1024/64, 2), 256>>>(p_h1 + 63*HH, TT*HH, C1W, HH, C1b, nullptr,
                                           p_t1, HH, 1024, 0, 1);
    gemm_kernel<<<dim3(512/64, 2), 256>>>(p_t1, 1024, C2W, 1024, C2b, nullptr,
                                          p_t2, 1024, 512, 0, 1);
    fc_kernel<<<32, 256>>>(p_t2, 512, CoW, 512, Cob, out + OG_OFF, 2, 128, 2, 512);

    gemm_kernel<<<dim3(1024/64, 2), 256>>>(p_h2 + 63*HH, TT*HH, C1W, HH, C1b, nullptr,
                                           p_t1, HH, 1024, 0, 1);
    gemm_kernel<<<dim3(512/64, 2), 256>>>(p_t1, 1024, C2W, 1024, C2b, nullptr,
                                          p_t2, 1024, 512, 0, 1);
    fc_kernel<<<32, 256>>>(p_t2, 512, CoW, 512, Cob, out + FAKE_OFF, 2, 128, 2, 512);
}